// round 3
// baseline (speedup 1.0000x reference)
#include <cuda_runtime.h>
#include <cstdint>

#define B_ 128
#define T_ 500
#define D_ 700
#define H_ 512
#define O_ 20

// ---------------- scratch (static device globals: no allocation allowed) ----------------
__device__ float          g_cur1[(size_t)T_ * B_ * H_];   // 131 MB  [t][b][h]
__device__ float          g_W1T[D_ * H_];                 // W1 transposed: [d][h]
__device__ float          g_W2T[H_ * H_];                 // W2 transposed: [h][g]
__device__ unsigned short g_idx[(size_t)B_ * T_ * H_];    // active-h lists per (b,t)
__device__ int            g_cnt[B_ * T_];                 // list lengths
__device__ float          g_S2[B_ * H_];                  // sum over t of s2

// ---------------- f32x2 helpers (Blackwell packed fp32) ----------------
__device__ __forceinline__ unsigned long long pack2(float x, float y) {
    unsigned long long r;
    asm("mov.b64 %0, {%1, %2};" : "=l"(r) : "f"(x), "f"(y));
    return r;
}
__device__ __forceinline__ void unpack2(unsigned long long p, float& x, float& y) {
    asm("mov.b64 {%0, %1}, %2;" : "=f"(x), "=f"(y) : "l"(p));
}
__device__ __forceinline__ void fma2(unsigned long long& d, unsigned long long a,
                                     unsigned long long b) {
    asm("fma.rn.f32x2 %0, %1, %2, %0;" : "+l"(d) : "l"(a), "l"(b));
}

// ---------------- weight transposes (tiny, run per launch, deterministic) ----------------
__global__ void transpose_w1(const float* __restrict__ W1) {
    int i = blockIdx.x * blockDim.x + threadIdx.x;
    if (i < D_ * H_) {
        int d = i / H_, h = i % H_;
        g_W1T[i] = W1[h * D_ + d];
    }
}
__global__ void transpose_w2(const float* __restrict__ W2) {
    int i = blockIdx.x * blockDim.x + threadIdx.x;
    if (i < H_ * H_) {
        int h = i / H_, g = i % H_;
        g_W2T[i] = W2[g * H_ + h];
    }
}

// ---------------- GEMM1: cur1[t,b,h] = x[b,t,:] . W1[h,:] + b1[h] ----------------
// Block tile: 128 (b) x 128 (h), K-tile 16, 256 threads, 8x8 per thread via f32x2 pairs.
// grid = (H/128=4, T=500): blockIdx.y == t, so A-tile rows are x[b, t, :], b = 0..127.
#define KT 16
#define NKT 44  // ceil(700/16)

__global__ __launch_bounds__(256, 2) void gemm1_kernel(const float* __restrict__ x,
                                                       const float* __restrict__ b1) {
    __shared__ float As[2][KT][128];  // [k][b]
    __shared__ float Bs[2][KT][128];  // [k][h]

    const int t     = blockIdx.y;
    const int hbase = blockIdx.x * 128;
    const int tid   = threadIdx.x;
    const int tx    = tid & 15;   // h micro-tile
    const int ty    = tid >> 4;   // b micro-tile

    // A loader: row = tid>>1 (b), two float4 at k offsets aK, aK+4
    const int aRow = tid >> 1;
    const int aK   = (tid & 1) << 3;
    const float* aBase = x + ((size_t)aRow * T_ + t) * D_;

    // B loader: two float4, linear l = it*1024 + tid*4 -> k = l>>7, h = l&127
    const int bK = (tid * 4) >> 7;     // 0..7 (second load at bK+8)
    const int bH = (tid * 4) & 127;
    const float* bBase = g_W1T + hbase + bH;

    const float4 f4zero = make_float4(0.f, 0.f, 0.f, 0.f);
    float4 pa0, pa1, pb0, pb1;

    unsigned long long acc[8][4];
#pragma unroll
    for (int i = 0; i < 8; i++)
#pragma unroll
        for (int j = 0; j < 4; j++) acc[i][j] = 0ull;

#define LOADTILE(k0)                                                                   \
    do {                                                                               \
        int ka = (k0) + aK;                                                            \
        pa0 = (ka     < D_) ? *(const float4*)(aBase + ka)     : f4zero;               \
        pa1 = (ka + 4 < D_) ? *(const float4*)(aBase + ka + 4) : f4zero;               \
        int kb = (k0) + bK;                                                            \
        pb0 = (kb     < D_) ? *(const float4*)(bBase + (size_t)kb * H_)       : f4zero;\
        pb1 = (kb + 8 < D_) ? *(const float4*)(bBase + (size_t)(kb + 8) * H_) : f4zero;\
    } while (0)

#define STORETILE(bi)                                                                  \
    do {                                                                               \
        As[bi][aK + 0][aRow] = pa0.x; As[bi][aK + 1][aRow] = pa0.y;                    \
        As[bi][aK + 2][aRow] = pa0.z; As[bi][aK + 3][aRow] = pa0.w;                    \
        As[bi][aK + 4][aRow] = pa1.x; As[bi][aK + 5][aRow] = pa1.y;                    \
        As[bi][aK + 6][aRow] = pa1.z; As[bi][aK + 7][aRow] = pa1.w;                    \
        *(float4*)&Bs[bi][bK][bH]     = pb0;                                           \
        *(float4*)&Bs[bi][bK + 8][bH] = pb1;                                           \
    } while (0)

    LOADTILE(0);
    STORETILE(0);
    __syncthreads();

    for (int kt = 0; kt < NKT; kt++) {
        const int buf = kt & 1;
        if (kt + 1 < NKT) LOADTILE((kt + 1) * KT);

#pragma unroll
        for (int k = 0; k < KT; k++) {
            const float* arow = &As[buf][k][ty * 8];
            float4 a0 = *(const float4*)arow;
            float4 a1 = *(const float4*)(arow + 4);
            const unsigned long long* bp = (const unsigned long long*)&Bs[buf][k][tx * 8];
            unsigned long long b0 = bp[0], b1v = bp[1], b2v = bp[2], b3v = bp[3];
            unsigned long long ap;
            ap = pack2(a0.x, a0.x);
            fma2(acc[0][0], ap, b0); fma2(acc[0][1], ap, b1v);
            fma2(acc[0][2], ap, b2v); fma2(acc[0][3], ap, b3v);
            ap = pack2(a0.y, a0.y);
            fma2(acc[1][0], ap, b0); fma2(acc[1][1], ap, b1v);
            fma2(acc[1][2], ap, b2v); fma2(acc[1][3], ap, b3v);
            ap = pack2(a0.z, a0.z);
            fma2(acc[2][0], ap, b0); fma2(acc[2][1], ap, b1v);
            fma2(acc[2][2], ap, b2v); fma2(acc[2][3], ap, b3v);
            ap = pack2(a0.w, a0.w);
            fma2(acc[3][0], ap, b0); fma2(acc[3][1], ap, b1v);
            fma2(acc[3][2], ap, b2v); fma2(acc[3][3], ap, b3v);
            ap = pack2(a1.x, a1.x);
            fma2(acc[4][0], ap, b0); fma2(acc[4][1], ap, b1v);
            fma2(acc[4][2], ap, b2v); fma2(acc[4][3], ap, b3v);
            ap = pack2(a1.y, a1.y);
            fma2(acc[5][0], ap, b0); fma2(acc[5][1], ap, b1v);
            fma2(acc[5][2], ap, b2v); fma2(acc[5][3], ap, b3v);
            ap = pack2(a1.z, a1.z);
            fma2(acc[6][0], ap, b0); fma2(acc[6][1], ap, b1v);
            fma2(acc[6][2], ap, b2v); fma2(acc[6][3], ap, b3v);
            ap = pack2(a1.w, a1.w);
            fma2(acc[7][0], ap, b0); fma2(acc[7][1], ap, b1v);
            fma2(acc[7][2], ap, b2v); fma2(acc[7][3], ap, b3v);
        }

        if (kt + 1 < NKT) STORETILE(buf ^ 1);
        __syncthreads();
    }

    // epilogue: + b1, write cur1[t][row][h]
    const float4 bv0 = *(const float4*)(b1 + hbase + tx * 8);
    const float4 bv1 = *(const float4*)(b1 + hbase + tx * 8 + 4);
#pragma unroll
    for (int i = 0; i < 8; i++) {
        int row = ty * 8 + i;
        float* o = g_cur1 + ((size_t)(t * B_ + row)) * H_ + hbase + tx * 8;
        float c0, c1, c2, c3, c4, c5, c6, c7;
        unpack2(acc[i][0], c0, c1);
        unpack2(acc[i][1], c2, c3);
        unpack2(acc[i][2], c4, c5);
        unpack2(acc[i][3], c6, c7);
        float4 r0 = make_float4(c0 + bv0.x, c1 + bv0.y, c2 + bv0.z, c3 + bv0.w);
        float4 r1 = make_float4(c4 + bv1.x, c5 + bv1.y, c6 + bv1.z, c7 + bv1.w);
        *(float4*)o       = r0;
        *(float4*)(o + 4) = r1;
    }
}

// ---------------- scan1: LIF over cur1, emit compact active-h lists per (b,t) ----------
// 128 blocks (one per b), 512 threads (one per h). Ballot-ordered compaction
// (h ascending) -> deterministic list order -> deterministic fp sums downstream.
__global__ void scan1_kernel() {
    const int b    = blockIdx.x;
    const int tid  = threadIdx.x;
    const int lane = tid & 31;
    const int warp = tid >> 5;
    __shared__ int wcnt[16];

    float v = 0.f;
    for (int t = 0; t < T_; t++) {
        float I = g_cur1[((size_t)t * B_ + b) * H_ + tid];
        v += (I - v) * 0.5f;                 // v + (I - v)/TAU, TAU=2
        bool s = (v >= 1.0f);
        unsigned mask = __ballot_sync(0xffffffffu, s);
        if (lane == 0) wcnt[warp] = __popc(mask);
        __syncthreads();
        if (s) {
            int off = 0;
#pragma unroll
            for (int w = 0; w < 16; w++)
                if (w < warp) off += wcnt[w];
            int pos = off + __popc(mask & ((1u << lane) - 1u));
            g_idx[(size_t)(b * T_ + t) * H_ + pos] = (unsigned short)tid;
            v = 0.f;                         // hard reset
        }
        if (tid == 0) {
            int tot = 0;
#pragma unroll
            for (int w = 0; w < 16; w++) tot += wcnt[w];
            g_cnt[b * T_ + t] = tot;
        }
        __syncthreads();
    }
}

// ---------------- layer2: sparse GEMM2 + LIF scan2 + time-sum of s2, fully fused -------
// grid (4, 128): blockIdx.y = b, blockIdx.x = g-quarter; 128 threads, one g each.
// cur2[t,b,g] = b2[g] + sum over active h of W2T[h][g]; membrane + spike count in regs.
__global__ void layer2_kernel(const float* __restrict__ b2) {
    const int b = blockIdx.y;
    const int g = blockIdx.x * 128 + threadIdx.x;
    const float bb = b2[g];
    const float* wcol = g_W2T + g;     // column g: W2T[h*H_ + g]
    float v = 0.f, s2c = 0.f;
    const int base = b * T_;
    for (int t = 0; t < T_; t++) {
        const int cnt = __ldg(&g_cnt[base + t]);
        const unsigned short* lp = g_idx + (size_t)(base + t) * H_;
        float cur = bb;
        int i = 0;
        for (; i + 4 <= cnt; i += 4) {
            int h0 = lp[i], h1 = lp[i + 1], h2 = lp[i + 2], h3 = lp[i + 3];
            float w0 = wcol[h0 * H_], w1 = wcol[h1 * H_];
            float w2v = wcol[h2 * H_], w3v = wcol[h3 * H_];
            cur += w0; cur += w1; cur += w2v; cur += w3v;
        }
        for (; i < cnt; i++) cur += wcol[(int)lp[i] * H_];
        v += (cur - v) * 0.5f;
        if (v >= 1.0f) { v = 0.f; s2c += 1.f; }
    }
    g_S2[b * H_ + g] = s2c;
}

// ---------------- final: out[b,o] = 500*b3[o] + sum_h S2[b,h] * W3[o,h] ----------------
__global__ void final_kernel(const float* __restrict__ W3, const float* __restrict__ b3,
                             float* __restrict__ out) {
    __shared__ float sW3[O_ * H_];
    __shared__ float part[4 * O_];
    const int b = blockIdx.x, tid = threadIdx.x;
    for (int i = tid; i < O_ * H_; i += 128) sW3[i] = W3[i];
    __syncthreads();

    float acc[O_];
#pragma unroll
    for (int o = 0; o < O_; o++) acc[o] = 0.f;
    for (int h = tid; h < H_; h += 128) {
        float s2 = g_S2[b * H_ + h];
#pragma unroll
        for (int o = 0; o < O_; o++) acc[o] += s2 * sW3[o * H_ + h];
    }
#pragma unroll
    for (int off = 16; off; off >>= 1)
#pragma unroll
        for (int o = 0; o < O_; o++)
            acc[o] += __shfl_down_sync(0xffffffffu, acc[o], off);
    if ((tid & 31) == 0)
#pragma unroll
        for (int o = 0; o < O_; o++) part[(tid >> 5) * O_ + o] = acc[o];
    __syncthreads();
    if (tid < O_) {
        float r = 500.0f * b3[tid];
#pragma unroll
        for (int w = 0; w < 4; w++) r += part[w * O_ + tid];
        out[b * O_ + tid] = r;
    }
}

// ---------------- launch ----------------
extern "C" void kernel_launch(void* const* d_in, const int* in_sizes, int n_in,
                              void* d_out, int out_size) {
    const float* x  = (const float*)d_in[0];   // [128, 500, 700]
    const float* W1 = (const float*)d_in[1];   // [512, 700]
    const float* b1 = (const float*)d_in[2];   // [512]
    const float* W2 = (const float*)d_in[3];   // [512, 512]
    const float* b2 = (const float*)d_in[4];   // [512]
    const float* W3 = (const float*)d_in[5];   // [20, 512]
    const float* b3 = (const float*)d_in[6];   // [20]
    float* out = (float*)d_out;                // [128, 20]

    transpose_w1<<<(D_ * H_ + 255) / 256, 256>>>(W1);
    transpose_w2<<<(H_ * H_ + 255) / 256, 256>>>(W2);
    gemm1_kernel<<<dim3(H_ / 128, T_), 256>>>(x, b1);
    scan1_kernel<<<B_, H_>>>();
    layer2_kernel<<<dim3(H_ / 128, B_), 128>>>(b2);
    final_kernel<<<B_, 128>>>(W3, b3, out);
}